// round 1
// baseline (speedup 1.0000x reference)
#include <cuda_runtime.h>
#include <cstdint>

// ---------------------------------------------------------------------------
// LinearAttention pipeline, tf32 mma.sync (m16n8k8), fp32 accumulate.
//   GEMM1: qkv[b]  = w_qkv[1536,256] @ x[b][256,4096]          (NN)
//   softmax over n on k rows (o in [512,1024))
//   GEMM2: ctxT[b,h][e,d] = sum_n v[e,n]*k[d,n]   split-K(8)   (NT)
//   GEMM3: attn[b,h][e,n] = sum_d ctxT[e,d]*q[d,n]             (NN)
//   GEMM4: out[b]  = w_out[256,512] @ attn[b][512,4096] + bias (NN)
// ---------------------------------------------------------------------------

#define BDIM   8
#define CIN    256
#define NPIX   4096
#define HEADS  4
#define DIMH   128
#define HID    512          // HEADS*DIMH
#define QKVR   1536         // 3*HID
#define KSPLIT 8

// scratch (device globals: no allocation allowed)
__device__ float g_qkv [(size_t)BDIM * QKVR * NPIX];                 // ~201 MB
__device__ float g_attn[(size_t)BDIM * HID  * NPIX];                 // ~67 MB
__device__ float g_ctx_part[KSPLIT][BDIM * HEADS][DIMH][DIMH];       // ~16.8 MB
__device__ float g_ctxT[BDIM * HEADS][DIMH][DIMH];                   // 2 MB

__device__ __forceinline__ uint32_t f2tf32(float x) {
    uint32_t u;
    asm("cvt.rna.tf32.f32 %0, %1;" : "=r"(u) : "f"(x));
    return u;
}

__device__ __forceinline__ void mma8(float c[4], const uint32_t a[4], const uint32_t b[2]) {
    asm volatile(
        "mma.sync.aligned.m16n8k8.row.col.f32.tf32.tf32.f32 "
        "{%0,%1,%2,%3}, {%4,%5,%6,%7}, {%8,%9}, {%0,%1,%2,%3};"
        : "+f"(c[0]), "+f"(c[1]), "+f"(c[2]), "+f"(c[3])
        : "r"(a[0]), "r"(a[1]), "r"(a[2]), "r"(a[3]), "r"(b[0]), "r"(b[1]));
}

// ---------------------------------------------------------------------------
// Generic NN GEMM: C = A[M,K] @ B[K,N] (+bias), 128x128 block, BK=16.
// blockIdx.z decomposed as (zo = z/zdiv, zi = z%zdiv), two-level strides.
// Requires M%128==0, N%128==0, K%16==0 (true for all call sites).
// ---------------------------------------------------------------------------
__global__ __launch_bounds__(256) void gemm_nn(
    const float* __restrict__ A, long long sA1, long long sA2,
    const float* __restrict__ B, long long sB1, long long sB2,
    float*       __restrict__ C, long long sC1, long long sC2,
    const float* __restrict__ bias,
    int zdiv, int M, int N, int K)
{
    const int bm = blockIdx.y, bn = blockIdx.x;
    const int zo = blockIdx.z / zdiv, zi = blockIdx.z % zdiv;
    A += zo * sA1 + zi * sA2;
    B += zo * sB1 + zi * sB2;
    C += zo * sC1 + zi * sC2;

    __shared__ uint32_t As[16][136];   // [k][m], stride 136 -> conflict-free frags
    __shared__ uint32_t Bs[16][136];   // [k][n]

    const int tid  = threadIdx.x;
    const int lane = tid & 31, warp = tid >> 5;
    const int g    = lane >> 2, t4 = lane & 3;
    const int wm   = warp & 3,  wn = warp >> 2;   // 4x2 warp grid

    float acc[2][8][4];
#pragma unroll
    for (int i = 0; i < 2; i++)
#pragma unroll
        for (int j = 0; j < 8; j++)
#pragma unroll
            for (int q = 0; q < 4; q++) acc[i][j][q] = 0.f;

    const int ar = tid >> 2;            // 0..63
    const int ac = (tid & 3) * 4;       // 0,4,8,12
    const int br = tid >> 5;            // 0..7
    const int bc = (tid & 31) * 4;      // 0..124

    const float* Ag = A + (long long)(bm * 128 + ar) * K + ac;
    const float* Bg = B + (long long)br * N + bn * 128 + bc;

    for (int k0 = 0; k0 < K; k0 += 16) {
        float4 a0 = *(const float4*)(Ag + k0);
        float4 a1 = *(const float4*)(Ag + 64ll * K + k0);
        float4 b0 = *(const float4*)(Bg + (long long)k0 * N);
        float4 b1 = *(const float4*)(Bg + (long long)(k0 + 8) * N);

        As[ac + 0][ar]      = f2tf32(a0.x);
        As[ac + 1][ar]      = f2tf32(a0.y);
        As[ac + 2][ar]      = f2tf32(a0.z);
        As[ac + 3][ar]      = f2tf32(a0.w);
        As[ac + 0][ar + 64] = f2tf32(a1.x);
        As[ac + 1][ar + 64] = f2tf32(a1.y);
        As[ac + 2][ar + 64] = f2tf32(a1.z);
        As[ac + 3][ar + 64] = f2tf32(a1.w);

        Bs[br][bc + 0]     = f2tf32(b0.x);
        Bs[br][bc + 1]     = f2tf32(b0.y);
        Bs[br][bc + 2]     = f2tf32(b0.z);
        Bs[br][bc + 3]     = f2tf32(b0.w);
        Bs[br + 8][bc + 0] = f2tf32(b1.x);
        Bs[br + 8][bc + 1] = f2tf32(b1.y);
        Bs[br + 8][bc + 2] = f2tf32(b1.z);
        Bs[br + 8][bc + 3] = f2tf32(b1.w);

        __syncthreads();

#pragma unroll
        for (int k8 = 0; k8 < 16; k8 += 8) {
            uint32_t af[2][4], bf[8][2];
#pragma unroll
            for (int im = 0; im < 2; im++) {
                int m = wm * 32 + im * 16 + g;
                af[im][0] = As[k8 + t4][m];
                af[im][1] = As[k8 + t4][m + 8];
                af[im][2] = As[k8 + t4 + 4][m];
                af[im][3] = As[k8 + t4 + 4][m + 8];
            }
#pragma unroll
            for (int in = 0; in < 8; in++) {
                int n = wn * 64 + in * 8 + g;
                bf[in][0] = Bs[k8 + t4][n];
                bf[in][1] = Bs[k8 + t4 + 4][n];
            }
#pragma unroll
            for (int im = 0; im < 2; im++)
#pragma unroll
                for (int in = 0; in < 8; in++)
                    mma8(acc[im][in], af[im], bf[in]);
        }
        __syncthreads();
    }

#pragma unroll
    for (int im = 0; im < 2; im++) {
        int m0 = bm * 128 + wm * 32 + im * 16 + g;
        float bia0 = bias ? bias[m0]     : 0.f;
        float bia1 = bias ? bias[m0 + 8] : 0.f;
#pragma unroll
        for (int in = 0; in < 8; in++) {
            int n0 = bn * 128 + wn * 64 + in * 8 + t4 * 2;
            float2 r0 = make_float2(acc[im][in][0] + bia0, acc[im][in][1] + bia0);
            float2 r1 = make_float2(acc[im][in][2] + bia1, acc[im][in][3] + bia1);
            *(float2*)(C + (long long)m0 * N + n0)       = r0;
            *(float2*)(C + (long long)(m0 + 8) * N + n0) = r1;
        }
    }
}

// ---------------------------------------------------------------------------
// GEMM2 (NT, split-K): ctx_part[slice][bh][e][d] = sum_{k slice} v[e,k]*k_sm[d,k]
// One block per (slice, bh). M=N=128, K-slice=512.
// ---------------------------------------------------------------------------
__global__ __launch_bounds__(256) void gemm_nt_ctx()
{
    const int slice = blockIdx.x;          // 0..KSPLIT-1
    const int bh    = blockIdx.y;          // 0..31
    const int b = bh >> 2, h = bh & 3;

    const float* Av = g_qkv + ((long long)b * QKVR + 1024 + h * 128) * NPIX;  // v rows (e)
    const float* Bk = g_qkv + ((long long)b * QKVR +  512 + h * 128) * NPIX;  // k rows (d)
    float* C = &g_ctx_part[slice][bh][0][0];

    __shared__ uint32_t As[16][136];   // [k][e]
    __shared__ uint32_t Bs[128][20];   // [d][k]

    const int tid  = threadIdx.x;
    const int lane = tid & 31, warp = tid >> 5;
    const int g    = lane >> 2, t4 = lane & 3;
    const int wm   = warp & 3,  wn = warp >> 2;

    float acc[2][8][4];
#pragma unroll
    for (int i = 0; i < 2; i++)
#pragma unroll
        for (int j = 0; j < 8; j++)
#pragma unroll
            for (int q = 0; q < 4; q++) acc[i][j][q] = 0.f;

    const int ar = tid >> 2;
    const int ac = (tid & 3) * 4;

    const int kbeg = slice * (NPIX / KSPLIT);
    const int kend = kbeg + (NPIX / KSPLIT);

    for (int k0 = kbeg; k0 < kend; k0 += 16) {
        float4 a0 = *(const float4*)(Av + (long long)ar * NPIX + k0 + ac);
        float4 a1 = *(const float4*)(Av + (long long)(ar + 64) * NPIX + k0 + ac);
        float4 b0 = *(const float4*)(Bk + (long long)ar * NPIX + k0 + ac);
        float4 b1 = *(const float4*)(Bk + (long long)(ar + 64) * NPIX + k0 + ac);

        As[ac + 0][ar]      = f2tf32(a0.x);
        As[ac + 1][ar]      = f2tf32(a0.y);
        As[ac + 2][ar]      = f2tf32(a0.z);
        As[ac + 3][ar]      = f2tf32(a0.w);
        As[ac + 0][ar + 64] = f2tf32(a1.x);
        As[ac + 1][ar + 64] = f2tf32(a1.y);
        As[ac + 2][ar + 64] = f2tf32(a1.z);
        As[ac + 3][ar + 64] = f2tf32(a1.w);

        Bs[ar][ac + 0]      = f2tf32(b0.x);
        Bs[ar][ac + 1]      = f2tf32(b0.y);
        Bs[ar][ac + 2]      = f2tf32(b0.z);
        Bs[ar][ac + 3]      = f2tf32(b0.w);
        Bs[ar + 64][ac + 0] = f2tf32(b1.x);
        Bs[ar + 64][ac + 1] = f2tf32(b1.y);
        Bs[ar + 64][ac + 2] = f2tf32(b1.z);
        Bs[ar + 64][ac + 3] = f2tf32(b1.w);

        __syncthreads();

#pragma unroll
        for (int k8 = 0; k8 < 16; k8 += 8) {
            uint32_t af[2][4], bf[8][2];
#pragma unroll
            for (int im = 0; im < 2; im++) {
                int m = wm * 32 + im * 16 + g;
                af[im][0] = As[k8 + t4][m];
                af[im][1] = As[k8 + t4][m + 8];
                af[im][2] = As[k8 + t4 + 4][m];
                af[im][3] = As[k8 + t4 + 4][m + 8];
            }
#pragma unroll
            for (int in = 0; in < 8; in++) {
                int n = wn * 64 + in * 8 + g;
                bf[in][0] = Bs[n][k8 + t4];
                bf[in][1] = Bs[n][k8 + t4 + 4];
            }
#pragma unroll
            for (int im = 0; im < 2; im++)
#pragma unroll
                for (int in = 0; in < 8; in++)
                    mma8(acc[im][in], af[im], bf[in]);
        }
        __syncthreads();
    }

#pragma unroll
    for (int im = 0; im < 2; im++) {
        int m0 = wm * 32 + im * 16 + g;
#pragma unroll
        for (int in = 0; in < 8; in++) {
            int n0 = wn * 64 + in * 8 + t4 * 2;
            *(float2*)(C + m0 * 128 + n0)       = make_float2(acc[im][in][0], acc[im][in][1]);
            *(float2*)(C + (m0 + 8) * 128 + n0) = make_float2(acc[im][in][2], acc[im][in][3]);
        }
    }
}

__global__ __launch_bounds__(256) void reduce_ctx()
{
    const long long i = (long long)blockIdx.x * 256 + threadIdx.x;
    const long long total = (long long)BDIM * HEADS * DIMH * DIMH;
    if (i >= total) return;
    const float* p = &g_ctx_part[0][0][0][0];
    float s = 0.f;
#pragma unroll
    for (int k = 0; k < KSPLIT; k++) s += p[(long long)k * total + i];
    (&g_ctxT[0][0][0])[i] = s;
}

// ---------------------------------------------------------------------------
// In-place softmax over n (4096) for k rows of g_qkv (one block per row).
// ---------------------------------------------------------------------------
__global__ __launch_bounds__(256) void softmax_k()
{
    const int r = blockIdx.x;                 // 0..4095 (b,h,d)
    const int b = r >> 9;
    const int o = 512 + (r & 511);
    float* row = g_qkv + ((long long)b * QKVR + o) * NPIX;

    __shared__ float sh[NPIX];
    __shared__ float red[8];
    const int tid = threadIdx.x;

    float mx = -1e30f;
    for (int i = tid; i < NPIX; i += 256) {
        float v = row[i];
        sh[i] = v;
        mx = fmaxf(mx, v);
    }
#pragma unroll
    for (int off = 16; off; off >>= 1) mx = fmaxf(mx, __shfl_xor_sync(0xffffffffu, mx, off));
    if ((tid & 31) == 0) red[tid >> 5] = mx;
    __syncthreads();
    float m = red[0];
#pragma unroll
    for (int i = 1; i < 8; i++) m = fmaxf(m, red[i]);
    __syncthreads();

    float s = 0.f;
    for (int i = tid; i < NPIX; i += 256) {
        float e = expf(sh[i] - m);
        sh[i] = e;
        s += e;
    }
#pragma unroll
    for (int off = 16; off; off >>= 1) s += __shfl_xor_sync(0xffffffffu, s, off);
    if ((tid & 31) == 0) red[tid >> 5] = s;
    __syncthreads();
    float tot = 0.f;
#pragma unroll
    for (int i = 0; i < 8; i++) tot += red[i];
    const float inv = 1.f / tot;

    for (int i = tid; i < NPIX; i += 256) row[i] = sh[i] * inv;
}

// ---------------------------------------------------------------------------
extern "C" void kernel_launch(void* const* d_in, const int* in_sizes, int n_in,
                              void* d_out, int out_size)
{
    (void)in_sizes; (void)n_in; (void)out_size;
    const float* x     = (const float*)d_in[0];   // [8,256,64,64]
    const float* w_qkv = (const float*)d_in[1];   // [1536,256]
    const float* w_out = (const float*)d_in[2];   // [256,512]
    const float* b_out = (const float*)d_in[3];   // [256]
    float* out = (float*)d_out;                   // [8,256,64,64]

    float *qkv_p = nullptr, *attn_p = nullptr, *ctxT_p = nullptr;
    cudaGetSymbolAddress((void**)&qkv_p,  g_qkv);
    cudaGetSymbolAddress((void**)&attn_p, g_attn);
    cudaGetSymbolAddress((void**)&ctxT_p, g_ctxT);

    dim3 blk(256);

    // GEMM1: qkv[b] = w_qkv @ x[b]
    gemm_nn<<<dim3(NPIX / 128, QKVR / 128, BDIM), blk>>>(
        w_qkv, 0, 0,
        x, (long long)CIN * NPIX, 0,
        qkv_p, (long long)QKVR * NPIX, 0,
        nullptr, 1, QKVR, NPIX, CIN);

    // softmax over n on k region
    softmax_k<<<BDIM * HEADS * DIMH, 256>>>();

    // GEMM2 (NT split-K) + reduce
    gemm_nt_ctx<<<dim3(KSPLIT, BDIM * HEADS), blk>>>();
    reduce_ctx<<<(BDIM * HEADS * DIMH * DIMH) / 256, 256>>>();

    // GEMM3: attn[b][h*128+e][n] = ctxT[b,h] @ q[b,h]
    gemm_nn<<<dim3(NPIX / 128, 1, BDIM * HEADS), blk>>>(
        ctxT_p, (long long)HEADS * DIMH * DIMH, (long long)DIMH * DIMH,
        qkv_p, (long long)QKVR * NPIX, (long long)DIMH * NPIX,
        attn_p, (long long)HID * NPIX, (long long)DIMH * NPIX,
        nullptr, HEADS, DIMH, NPIX, DIMH);

    // GEMM4: out[b] = w_out @ attn[b] + b_out
    gemm_nn<<<dim3(NPIX / 128, CIN / 128, BDIM), blk>>>(
        w_out, 0, 0,
        attn_p, (long long)HID * NPIX, 0,
        out, (long long)CIN * NPIX, 0,
        b_out, 1, CIN, NPIX, HID);
}

// round 2
// speedup vs baseline: 1.1858x; 1.1858x over previous
#include <cuda_runtime.h>
#include <cstdint>

// ---------------------------------------------------------------------------
// LinearAttention, tf32 mma.sync m16n8k8 + cp.async 3-stage pipelines.
//   pre-round x, w_qkv, w_out to tf32 (rna)
//   GEMM1: qkv[b]  = w_qkv @ x[b]                (NN, round output)
//   softmax over n on k rows                     (round output)
//   GEMM2: ctxT[e,d] = sum_n v[e,n]k[d,n]        (NT, split-K 8)
//   reduce partials                              (round output)
//   GEMM3: attn = ctxT @ q                       (NN, round output)
//   GEMM4: out  = w_out @ attn + bias            (NN, full fp32 out)
// ---------------------------------------------------------------------------

#define BDIM   8
#define CIN    256
#define NPIX   4096
#define HEADS  4
#define DIMH   128
#define HID    512
#define QKVR   1536
#define KSPLIT 8

#define SA    20            // A smem row stride (floats), [m][k] layout
#define SBN   136           // B smem row stride (floats), [k][n] layout
#define NSTG  3
#define A_STG (128 * SA)    // 2560 floats / stage
#define B_STG (16 * SBN)    // 2176 floats / stage
#define SMEM_NN (NSTG * (A_STG + B_STG) * 4)   // 56832 B
#define SMEM_NT (NSTG * (A_STG + A_STG) * 4)   // 61440 B

// scratch (device globals: no allocation allowed)
__device__ float g_qkv [(size_t)BDIM * QKVR * NPIX];
__device__ float g_attn[(size_t)BDIM * HID  * NPIX];
__device__ float g_ctx_part[KSPLIT][BDIM * HEADS][DIMH][DIMH];
__device__ float g_ctxT[BDIM * HEADS][DIMH][DIMH];
__device__ float g_xr  [(size_t)BDIM * CIN * NPIX];
__device__ float g_wq  [QKVR * CIN];
__device__ float g_wo  [CIN * HID];

__device__ __forceinline__ float rtf32(float x) {
    uint32_t u;
    asm("cvt.rna.tf32.f32 %0, %1;" : "=r"(u) : "f"(x));
    return __uint_as_float(u);
}
__device__ __forceinline__ void cpa16(uint32_t d, const float* s) {
    asm volatile("cp.async.cg.shared.global [%0], [%1], 16;\n" :: "r"(d), "l"(s));
}
__device__ __forceinline__ void cp_commit() { asm volatile("cp.async.commit_group;\n"); }
template<int N> __device__ __forceinline__ void cp_wait() {
    asm volatile("cp.async.wait_group %0;\n" :: "n"(N));
}

__device__ __forceinline__ void mma8(float c[4], const uint32_t a[4], const uint32_t b[2]) {
    asm volatile(
        "mma.sync.aligned.m16n8k8.row.col.f32.tf32.tf32.f32 "
        "{%0,%1,%2,%3}, {%4,%5,%6,%7}, {%8,%9}, {%0,%1,%2,%3};"
        : "+f"(c[0]), "+f"(c[1]), "+f"(c[2]), "+f"(c[3])
        : "r"(a[0]), "r"(a[1]), "r"(a[2]), "r"(a[3]), "r"(b[0]), "r"(b[1]));
}

// ---------------------------------------------------------------------------
// elementwise tf32 round (n4 = elems/4)
// ---------------------------------------------------------------------------
__global__ __launch_bounds__(256) void round_tf32(
    const float* __restrict__ in, float* __restrict__ out, int n4)
{
    int i = blockIdx.x * 256 + threadIdx.x;
    if (i < n4) {
        float4 v = ((const float4*)in)[i];
        v.x = rtf32(v.x); v.y = rtf32(v.y); v.z = rtf32(v.z); v.w = rtf32(v.w);
        ((float4*)out)[i] = v;
    }
}

// ---------------------------------------------------------------------------
// NN GEMM: C = A[M,K]@B[K,N] (+bias). 128x128 tile, BK=16, 3-stage cp.async.
// A row-major lda=K. z decomposed (zo=z/zdiv, zi=z%zdiv) two-level strides.
// ---------------------------------------------------------------------------
template<bool ROUND>
__global__ __launch_bounds__(256) void gemm_nn(
    const float* __restrict__ A, long long sA1, long long sA2,
    const float* __restrict__ B, long long sB1, long long sB2,
    float*       __restrict__ C, long long sC1, long long sC2,
    const float* __restrict__ bias,
    int zdiv, int N, int K)
{
    extern __shared__ float sm[];
    float* Asm = sm;                   // [NSTG][128][SA]
    float* Bsm = sm + NSTG * A_STG;    // [NSTG][16][SBN]

    const int bm = blockIdx.y, bn = blockIdx.x;
    const int zo = blockIdx.z / zdiv, zi = blockIdx.z % zdiv;
    A += zo * sA1 + zi * sA2;
    B += zo * sB1 + zi * sB2;
    C += zo * sC1 + zi * sC2;

    const int tid  = threadIdx.x;
    const int lane = tid & 31, warp = tid >> 5;
    const int g    = lane >> 2, t4 = lane & 3;
    const int wm   = warp & 3,  wn = warp >> 2;

    const float* Ag = A + (long long)bm * 128 * K;
    const float* Bg = B + bn * 128;

    const uint32_t asm0 = (uint32_t)__cvta_generic_to_shared(Asm);
    const uint32_t bsm0 = (uint32_t)__cvta_generic_to_shared(Bsm);

    const int lar = tid >> 2, lac = (tid & 3) * 4;   // A chunks: rows lar, lar+64
    const int lbr = tid >> 5, lbc = (tid & 31) * 4;  // B chunks: rows lbr, lbr+8

#define LD_NN(st, kk) do {                                                      \
    uint32_t ab = asm0 + (st) * (A_STG * 4);                                    \
    uint32_t bb = bsm0 + (st) * (B_STG * 4);                                    \
    cpa16(ab + (lar * SA + lac) * 4,        Ag + (long long)lar * K + (kk) + lac);        \
    cpa16(ab + ((lar + 64) * SA + lac) * 4, Ag + (long long)(lar + 64) * K + (kk) + lac); \
    cpa16(bb + (lbr * SBN + lbc) * 4,       Bg + (long long)((kk) + lbr) * N + lbc);      \
    cpa16(bb + ((lbr + 8) * SBN + lbc) * 4, Bg + (long long)((kk) + lbr + 8) * N + lbc);  \
    cp_commit();                                                                \
} while (0)

    float acc[2][8][4] = {};
    const int niter = K / 16;

    LD_NN(0, 0);
    LD_NN(1, 16);

    for (int it = 0; it < niter; ++it) {
        cp_wait<NSTG - 2>();
        __syncthreads();
        const int ls = it + NSTG - 1;
        if (ls < niter) { LD_NN(ls % NSTG, ls * 16); }
        else            { cp_commit(); }

        const float* As = Asm + (it % NSTG) * A_STG;
        const float* Bs = Bsm + (it % NSTG) * B_STG;

#pragma unroll
        for (int k8 = 0; k8 < 16; k8 += 8) {
            uint32_t af[2][4], bf[8][2];
#pragma unroll
            for (int im = 0; im < 2; im++) {
                int m = wm * 32 + im * 16 + g;
                af[im][0] = __float_as_uint(As[m * SA + k8 + t4]);
                af[im][1] = __float_as_uint(As[(m + 8) * SA + k8 + t4]);
                af[im][2] = __float_as_uint(As[m * SA + k8 + t4 + 4]);
                af[im][3] = __float_as_uint(As[(m + 8) * SA + k8 + t4 + 4]);
            }
#pragma unroll
            for (int in = 0; in < 8; in++) {
                int n = wn * 64 + in * 8 + g;
                bf[in][0] = __float_as_uint(Bs[(k8 + t4) * SBN + n]);
                bf[in][1] = __float_as_uint(Bs[(k8 + t4 + 4) * SBN + n]);
            }
#pragma unroll
            for (int im = 0; im < 2; im++)
#pragma unroll
                for (int in = 0; in < 8; in++)
                    mma8(acc[im][in], af[im], bf[in]);
        }
    }
#undef LD_NN

#pragma unroll
    for (int im = 0; im < 2; im++) {
        int m0 = bm * 128 + wm * 32 + im * 16 + g;
        float bv0 = bias ? bias[m0]     : 0.f;
        float bv1 = bias ? bias[m0 + 8] : 0.f;
#pragma unroll
        for (int in = 0; in < 8; in++) {
            int n0 = bn * 128 + wn * 64 + in * 8 + t4 * 2;
            float v0 = acc[im][in][0] + bv0, v1 = acc[im][in][1] + bv0;
            float v2 = acc[im][in][2] + bv1, v3 = acc[im][in][3] + bv1;
            if (ROUND) { v0 = rtf32(v0); v1 = rtf32(v1); v2 = rtf32(v2); v3 = rtf32(v3); }
            *(float2*)(C + (long long)m0 * N + n0)       = make_float2(v0, v1);
            *(float2*)(C + (long long)(m0 + 8) * N + n0) = make_float2(v2, v3);
        }
    }
}

// ---------------------------------------------------------------------------
// GEMM2 (NT, split-K): ctx_part[slice][bh][e][d] = sum_{n in slice} v[e,n]k[d,n]
// ---------------------------------------------------------------------------
__global__ __launch_bounds__(256) void gemm_nt_ctx()
{
    extern __shared__ float sm[];
    float* Asm = sm;                   // [NSTG][128][SA]  (v: [e][k])
    float* Bsm = sm + NSTG * A_STG;    // [NSTG][128][SA]  (k: [d][k])

    const int slice = blockIdx.x;
    const int bh    = blockIdx.y;
    const int b = bh >> 2, h = bh & 3;

    const float* Ag = g_qkv + ((long long)b * QKVR + 1024 + h * 128) * NPIX;
    const float* Bg = g_qkv + ((long long)b * QKVR +  512 + h * 128) * NPIX;
    float* C = &g_ctx_part[slice][bh][0][0];

    const int tid  = threadIdx.x;
    const int lane = tid & 31, warp = tid >> 5;
    const int g    = lane >> 2, t4 = lane & 3;
    const int wm   = warp & 3,  wn = warp >> 2;

    const uint32_t asm0 = (uint32_t)__cvta_generic_to_shared(Asm);
    const uint32_t bsm0 = (uint32_t)__cvta_generic_to_shared(Bsm);

    const int lar = tid >> 2, lac = (tid & 3) * 4;

#define LD_NT(st, kk) do {                                                      \
    uint32_t ab = asm0 + (st) * (A_STG * 4);                                    \
    uint32_t bb = bsm0 + (st) * (A_STG * 4);                                    \
    cpa16(ab + (lar * SA + lac) * 4,        Ag + (long long)lar * NPIX + (kk) + lac);        \
    cpa16(ab + ((lar + 64) * SA + lac) * 4, Ag + (long long)(lar + 64) * NPIX + (kk) + lac); \
    cpa16(bb + (lar * SA + lac) * 4,        Bg + (long long)lar * NPIX + (kk) + lac);        \
    cpa16(bb + ((lar + 64) * SA + lac) * 4, Bg + (long long)(lar + 64) * NPIX + (kk) + lac); \
    cp_commit();                                                                \
} while (0)

    float acc[2][8][4] = {};
    const int kbeg  = slice * (NPIX / KSPLIT);
    const int niter = (NPIX / KSPLIT) / 16;   // 32

    LD_NT(0, kbeg);
    LD_NT(1, kbeg + 16);

    for (int it = 0; it < niter; ++it) {
        cp_wait<NSTG - 2>();
        __syncthreads();
        const int ls = it + NSTG - 1;
        if (ls < niter) { LD_NT(ls % NSTG, kbeg + ls * 16); }
        else            { cp_commit(); }

        const float* As = Asm + (it % NSTG) * A_STG;
        const float* Bs = Bsm + (it % NSTG) * A_STG;

#pragma unroll
        for (int k8 = 0; k8 < 16; k8 += 8) {
            uint32_t af[2][4], bf[8][2];
#pragma unroll
            for (int im = 0; im < 2; im++) {
                int m = wm * 32 + im * 16 + g;
                af[im][0] = __float_as_uint(As[m * SA + k8 + t4]);
                af[im][1] = __float_as_uint(As[(m + 8) * SA + k8 + t4]);
                af[im][2] = __float_as_uint(As[m * SA + k8 + t4 + 4]);
                af[im][3] = __float_as_uint(As[(m + 8) * SA + k8 + t4 + 4]);
            }
#pragma unroll
            for (int in = 0; in < 8; in++) {
                int n = wn * 64 + in * 8 + g;
                bf[in][0] = __float_as_uint(Bs[n * SA + k8 + t4]);
                bf[in][1] = __float_as_uint(Bs[n * SA + k8 + t4 + 4]);
            }
#pragma unroll
            for (int im = 0; im < 2; im++)
#pragma unroll
                for (int in = 0; in < 8; in++)
                    mma8(acc[im][in], af[im], bf[in]);
        }
    }
#undef LD_NT

#pragma unroll
    for (int im = 0; im < 2; im++) {
        int m0 = wm * 32 + im * 16 + g;
#pragma unroll
        for (int in = 0; in < 8; in++) {
            int n0 = wn * 64 + in * 8 + t4 * 2;
            *(float2*)(C + m0 * 128 + n0)       = make_float2(acc[im][in][0], acc[im][in][1]);
            *(float2*)(C + (m0 + 8) * 128 + n0) = make_float2(acc[im][in][2], acc[im][in][3]);
        }
    }
}

__global__ __launch_bounds__(256) void reduce_ctx()
{
    const long long i = (long long)blockIdx.x * 256 + threadIdx.x;
    const long long total = (long long)BDIM * HEADS * DIMH * DIMH;
    if (i >= total) return;
    const float* p = &g_ctx_part[0][0][0][0];
    float s = 0.f;
#pragma unroll
    for (int k = 0; k < KSPLIT; k++) s += p[(long long)k * total + i];
    (&g_ctxT[0][0][0])[i] = rtf32(s);
}

// ---------------------------------------------------------------------------
// In-place softmax over n (4096) for k rows of g_qkv; stores tf32-rounded.
// ---------------------------------------------------------------------------
__global__ __launch_bounds__(256) void softmax_k()
{
    const int r = blockIdx.x;
    const int b = r >> 9;
    const int o = 512 + (r & 511);
    float* row = g_qkv + ((long long)b * QKVR + o) * NPIX;

    __shared__ float sh[NPIX];
    __shared__ float red[8];
    const int tid = threadIdx.x;

    float mx = -1e30f;
    for (int i = tid; i < NPIX; i += 256) {
        float v = row[i];
        sh[i] = v;
        mx = fmaxf(mx, v);
    }
#pragma unroll
    for (int off = 16; off; off >>= 1) mx = fmaxf(mx, __shfl_xor_sync(0xffffffffu, mx, off));
    if ((tid & 31) == 0) red[tid >> 5] = mx;
    __syncthreads();
    float m = red[0];
#pragma unroll
    for (int i = 1; i < 8; i++) m = fmaxf(m, red[i]);
    __syncthreads();

    float s = 0.f;
    for (int i = tid; i < NPIX; i += 256) {
        float e = __expf(sh[i] - m);
        sh[i] = e;
        s += e;
    }
#pragma unroll
    for (int off = 16; off; off >>= 1) s += __shfl_xor_sync(0xffffffffu, s, off);
    if ((tid & 31) == 0) red[tid >> 5] = s;
    __syncthreads();
    float tot = 0.f;
#pragma unroll
    for (int i = 0; i < 8; i++) tot += red[i];
    const float inv = 1.f / tot;

    for (int i = tid; i < NPIX; i += 256) row[i] = rtf32(sh[i] * inv);
}

// ---------------------------------------------------------------------------
extern "C" void kernel_launch(void* const* d_in, const int* in_sizes, int n_in,
                              void* d_out, int out_size)
{
    (void)in_sizes; (void)n_in; (void)out_size;
    const float* x     = (const float*)d_in[0];
    const float* w_qkv = (const float*)d_in[1];
    const float* w_out = (const float*)d_in[2];
    const float* b_out = (const float*)d_in[3];
    float* out = (float*)d_out;

    float *qkv_p, *attn_p, *ctxT_p, *xr_p, *wq_p, *wo_p;
    cudaGetSymbolAddress((void**)&qkv_p,  g_qkv);
    cudaGetSymbolAddress((void**)&attn_p, g_attn);
    cudaGetSymbolAddress((void**)&ctxT_p, g_ctxT);
    cudaGetSymbolAddress((void**)&xr_p,   g_xr);
    cudaGetSymbolAddress((void**)&wq_p,   g_wq);
    cudaGetSymbolAddress((void**)&wo_p,   g_wo);

    cudaFuncSetAttribute((const void*)gemm_nn<true>,
                         cudaFuncAttributeMaxDynamicSharedMemorySize, SMEM_NN);
    cudaFuncSetAttribute((const void*)gemm_nn<false>,
                         cudaFuncAttributeMaxDynamicSharedMemorySize, SMEM_NN);
    cudaFuncSetAttribute((const void*)gemm_nt_ctx,
                         cudaFuncAttributeMaxDynamicSharedMemorySize, SMEM_NT);

    dim3 blk(256);

    // pre-round inputs to tf32
    round_tf32<<<(BDIM * CIN * NPIX / 4 + 255) / 256, blk>>>(x, xr_p, BDIM * CIN * NPIX / 4);
    round_tf32<<<(QKVR * CIN / 4 + 255) / 256, blk>>>(w_qkv, wq_p, QKVR * CIN / 4);
    round_tf32<<<(CIN * HID / 4 + 255) / 256, blk>>>(w_out, wo_p, CIN * HID / 4);

    // GEMM1: qkv[b] = w_qkv @ x[b]   (round output)
    gemm_nn<true><<<dim3(NPIX / 128, QKVR / 128, BDIM), blk, SMEM_NN>>>(
        wq_p, 0, 0,
        xr_p, (long long)CIN * NPIX, 0,
        qkv_p, (long long)QKVR * NPIX, 0,
        nullptr, 1, NPIX, CIN);

    // softmax over n on k region (rounds output)
    softmax_k<<<BDIM * HEADS * DIMH, blk>>>();

    // GEMM2 (NT split-K) + rounded reduce
    gemm_nt_ctx<<<dim3(KSPLIT, BDIM * HEADS), blk, SMEM_NT>>>();
    reduce_ctx<<<(BDIM * HEADS * DIMH * DIMH) / 256, blk>>>();

    // GEMM3: attn[b,h] = ctxT[b,h] @ q[b,h]   (round output)
    gemm_nn<true><<<dim3(NPIX / 128, 1, BDIM * HEADS), blk, SMEM_NN>>>(
        ctxT_p, (long long)HEADS * DIMH * DIMH, (long long)DIMH * DIMH,
        qkv_p, (long long)QKVR * NPIX, (long long)DIMH * NPIX,
        attn_p, (long long)HID * NPIX, (long long)DIMH * NPIX,
        nullptr, HEADS, NPIX, DIMH);

    // GEMM4: out[b] = w_out @ attn[b] + b_out   (full fp32)
    gemm_nn<false><<<dim3(NPIX / 128, CIN / 128, BDIM), blk, SMEM_NN>>>(
        wo_p, 0, 0,
        attn_p, (long long)HID * NPIX, 0,
        out, (long long)CIN * NPIX, 0,
        b_out, 1, NPIX, HID);
}

// round 3
// speedup vs baseline: 1.1860x; 1.0002x over previous
#include <cuda_runtime.h>
#include <cstdint>

// ---------------------------------------------------------------------------
// LinearAttention, tf32 mma.sync m16n8k8 + cp.async 3-stage pipelines.
//   pre-round x, w_qkv, w_out to tf32 (rna)
//   GEMM1: qkv[b]  = w_qkv @ x[b]                (NN, round output)
//   softmax over n on k rows                     (round output)
//   GEMM2: ctxT[e,d] = sum_n v[e,n]k[d,n]        (NT, split-K 8)
//   reduce partials                              (round output)
//   GEMM3: attn = ctxT @ q                       (NN, round output)
//   GEMM4: out  = w_out @ attn + bias            (NN, full fp32 out)
// ---------------------------------------------------------------------------

#define BDIM   8
#define CIN    256
#define NPIX   4096
#define HEADS  4
#define DIMH   128
#define HID    512
#define QKVR   1536
#define KSPLIT 8

#define SA    20            // A smem row stride (floats), [m][k] layout
#define SBN   136           // B smem row stride (floats), [k][n] layout
#define NSTG  3
#define A_STG (128 * SA)    // 2560 floats / stage
#define B_STG (16 * SBN)    // 2176 floats / stage
#define SMEM_NN (NSTG * (A_STG + B_STG) * 4)   // 56832 B
#define SMEM_NT (NSTG * (A_STG + A_STG) * 4)   // 61440 B

// scratch (device globals: no allocation allowed)
__device__ float g_qkv [(size_t)BDIM * QKVR * NPIX];
__device__ float g_attn[(size_t)BDIM * HID  * NPIX];
__device__ float g_ctx_part[KSPLIT][BDIM * HEADS][DIMH][DIMH];
__device__ float g_ctxT[BDIM * HEADS][DIMH][DIMH];
__device__ float g_xr  [(size_t)BDIM * CIN * NPIX];
__device__ float g_wq  [QKVR * CIN];
__device__ float g_wo  [CIN * HID];

__device__ __forceinline__ float rtf32(float x) {
    uint32_t u;
    asm("cvt.rna.tf32.f32 %0, %1;" : "=r"(u) : "f"(x));
    return __uint_as_float(u);
}
__device__ __forceinline__ void cpa16(uint32_t d, const float* s) {
    asm volatile("cp.async.cg.shared.global [%0], [%1], 16;\n" :: "r"(d), "l"(s));
}
__device__ __forceinline__ void cp_commit() { asm volatile("cp.async.commit_group;\n"); }
template<int N> __device__ __forceinline__ void cp_wait() {
    asm volatile("cp.async.wait_group %0;\n" :: "n"(N));
}

__device__ __forceinline__ void mma8(float c[4], const uint32_t a[4], const uint32_t b[2]) {
    asm volatile(
        "mma.sync.aligned.m16n8k8.row.col.f32.tf32.tf32.f32 "
        "{%0,%1,%2,%3}, {%4,%5,%6,%7}, {%8,%9}, {%0,%1,%2,%3};"
        : "+f"(c[0]), "+f"(c[1]), "+f"(c[2]), "+f"(c[3])
        : "r"(a[0]), "r"(a[1]), "r"(a[2]), "r"(a[3]), "r"(b[0]), "r"(b[1]));
}

// ---------------------------------------------------------------------------
// elementwise tf32 round (n4 = elems/4)
// ---------------------------------------------------------------------------
__global__ __launch_bounds__(256) void round_tf32(
    const float* __restrict__ in, float* __restrict__ out, int n4)
{
    int i = blockIdx.x * 256 + threadIdx.x;
    if (i < n4) {
        float4 v = ((const float4*)in)[i];
        v.x = rtf32(v.x); v.y = rtf32(v.y); v.z = rtf32(v.z); v.w = rtf32(v.w);
        ((float4*)out)[i] = v;
    }
}

// ---------------------------------------------------------------------------
// NN GEMM: C = A[M,K]@B[K,N] (+bias). 128x128 tile, BK=16, 3-stage cp.async.
// A row-major lda=K. z decomposed (zo=z/zdiv, zi=z%zdiv) two-level strides.
// ---------------------------------------------------------------------------
template<bool ROUND>
__global__ __launch_bounds__(256) void gemm_nn(
    const float* __restrict__ A, long long sA1, long long sA2,
    const float* __restrict__ B, long long sB1, long long sB2,
    float*       __restrict__ C, long long sC1, long long sC2,
    const float* __restrict__ bias,
    int zdiv, int N, int K)
{
    extern __shared__ float sm[];
    float* Asm = sm;                   // [NSTG][128][SA]
    float* Bsm = sm + NSTG * A_STG;    // [NSTG][16][SBN]

    const int bm = blockIdx.y, bn = blockIdx.x;
    const int zo = blockIdx.z / zdiv, zi = blockIdx.z % zdiv;
    A += zo * sA1 + zi * sA2;
    B += zo * sB1 + zi * sB2;
    C += zo * sC1 + zi * sC2;

    const int tid  = threadIdx.x;
    const int lane = tid & 31, warp = tid >> 5;
    const int g    = lane >> 2, t4 = lane & 3;
    const int wm   = warp & 3,  wn = warp >> 2;

    const float* Ag = A + (long long)bm * 128 * K;
    const float* Bg = B + bn * 128;

    const uint32_t asm0 = (uint32_t)__cvta_generic_to_shared(Asm);
    const uint32_t bsm0 = (uint32_t)__cvta_generic_to_shared(Bsm);

    const int lar = tid >> 2, lac = (tid & 3) * 4;   // A chunks: rows lar, lar+64
    const int lbr = tid >> 5, lbc = (tid & 31) * 4;  // B chunks: rows lbr, lbr+8

#define LD_NN(st, kk) do {                                                      \
    uint32_t ab = asm0 + (st) * (A_STG * 4);                                    \
    uint32_t bb = bsm0 + (st) * (B_STG * 4);                                    \
    cpa16(ab + (lar * SA + lac) * 4,        Ag + (long long)lar * K + (kk) + lac);        \
    cpa16(ab + ((lar + 64) * SA + lac) * 4, Ag + (long long)(lar + 64) * K + (kk) + lac); \
    cpa16(bb + (lbr * SBN + lbc) * 4,       Bg + (long long)((kk) + lbr) * N + lbc);      \
    cpa16(bb + ((lbr + 8) * SBN + lbc) * 4, Bg + (long long)((kk) + lbr + 8) * N + lbc);  \
    cp_commit();                                                                \
} while (0)

    float acc[2][8][4] = {};
    const int niter = K / 16;

    LD_NN(0, 0);
    LD_NN(1, 16);

    for (int it = 0; it < niter; ++it) {
        cp_wait<NSTG - 2>();
        __syncthreads();
        const int ls = it + NSTG - 1;
        if (ls < niter) { LD_NN(ls % NSTG, ls * 16); }
        else            { cp_commit(); }

        const float* As = Asm + (it % NSTG) * A_STG;
        const float* Bs = Bsm + (it % NSTG) * B_STG;

#pragma unroll
        for (int k8 = 0; k8 < 16; k8 += 8) {
            uint32_t af[2][4], bf[8][2];
#pragma unroll
            for (int im = 0; im < 2; im++) {
                int m = wm * 32 + im * 16 + g;
                af[im][0] = __float_as_uint(As[m * SA + k8 + t4]);
                af[im][1] = __float_as_uint(As[(m + 8) * SA + k8 + t4]);
                af[im][2] = __float_as_uint(As[m * SA + k8 + t4 + 4]);
                af[im][3] = __float_as_uint(As[(m + 8) * SA + k8 + t4 + 4]);
            }
#pragma unroll
            for (int in = 0; in < 8; in++) {
                int n = wn * 64 + in * 8 + g;
                bf[in][0] = __float_as_uint(Bs[(k8 + t4) * SBN + n]);
                bf[in][1] = __float_as_uint(Bs[(k8 + t4 + 4) * SBN + n]);
            }
#pragma unroll
            for (int im = 0; im < 2; im++)
#pragma unroll
                for (int in = 0; in < 8; in++)
                    mma8(acc[im][in], af[im], bf[in]);
        }
    }
#undef LD_NN

#pragma unroll
    for (int im = 0; im < 2; im++) {
        int m0 = bm * 128 + wm * 32 + im * 16 + g;
        float bv0 = bias ? bias[m0]     : 0.f;
        float bv1 = bias ? bias[m0 + 8] : 0.f;
#pragma unroll
        for (int in = 0; in < 8; in++) {
            int n0 = bn * 128 + wn * 64 + in * 8 + t4 * 2;
            float v0 = acc[im][in][0] + bv0, v1 = acc[im][in][1] + bv0;
            float v2 = acc[im][in][2] + bv1, v3 = acc[im][in][3] + bv1;
            if (ROUND) { v0 = rtf32(v0); v1 = rtf32(v1); v2 = rtf32(v2); v3 = rtf32(v3); }
            *(float2*)(C + (long long)m0 * N + n0)       = make_float2(v0, v1);
            *(float2*)(C + (long long)(m0 + 8) * N + n0) = make_float2(v2, v3);
        }
    }
}

// ---------------------------------------------------------------------------
// GEMM2 (NT, split-K): ctx_part[slice][bh][e][d] = sum_{n in slice} v[e,n]k[d,n]
// ---------------------------------------------------------------------------
__global__ __launch_bounds__(256) void gemm_nt_ctx()
{
    extern __shared__ float sm[];
    float* Asm = sm;                   // [NSTG][128][SA]  (v: [e][k])
    float* Bsm = sm + NSTG * A_STG;    // [NSTG][128][SA]  (k: [d][k])

    const int slice = blockIdx.x;
    const int bh    = blockIdx.y;
    const int b = bh >> 2, h = bh & 3;

    const float* Ag = g_qkv + ((long long)b * QKVR + 1024 + h * 128) * NPIX;
    const float* Bg = g_qkv + ((long long)b * QKVR +  512 + h * 128) * NPIX;
    float* C = &g_ctx_part[slice][bh][0][0];

    const int tid  = threadIdx.x;
    const int lane = tid & 31, warp = tid >> 5;
    const int g    = lane >> 2, t4 = lane & 3;
    const int wm   = warp & 3,  wn = warp >> 2;

    const uint32_t asm0 = (uint32_t)__cvta_generic_to_shared(Asm);
    const uint32_t bsm0 = (uint32_t)__cvta_generic_to_shared(Bsm);

    const int lar = tid >> 2, lac = (tid & 3) * 4;

#define LD_NT(st, kk) do {                                                      \
    uint32_t ab = asm0 + (st) * (A_STG * 4);                                    \
    uint32_t bb = bsm0 + (st) * (A_STG * 4);                                    \
    cpa16(ab + (lar * SA + lac) * 4,        Ag + (long long)lar * NPIX + (kk) + lac);        \
    cpa16(ab + ((lar + 64) * SA + lac) * 4, Ag + (long long)(lar + 64) * NPIX + (kk) + lac); \
    cpa16(bb + (lar * SA + lac) * 4,        Bg + (long long)lar * NPIX + (kk) + lac);        \
    cpa16(bb + ((lar + 64) * SA + lac) * 4, Bg + (long long)(lar + 64) * NPIX + (kk) + lac); \
    cp_commit();                                                                \
} while (0)

    float acc[2][8][4] = {};
    const int kbeg  = slice * (NPIX / KSPLIT);
    const int niter = (NPIX / KSPLIT) / 16;   // 32

    LD_NT(0, kbeg);
    LD_NT(1, kbeg + 16);

    for (int it = 0; it < niter; ++it) {
        cp_wait<NSTG - 2>();
        __syncthreads();
        const int ls = it + NSTG - 1;
        if (ls < niter) { LD_NT(ls % NSTG, kbeg + ls * 16); }
        else            { cp_commit(); }

        const float* As = Asm + (it % NSTG) * A_STG;
        const float* Bs = Bsm + (it % NSTG) * A_STG;

#pragma unroll
        for (int k8 = 0; k8 < 16; k8 += 8) {
            uint32_t af[2][4], bf[8][2];
#pragma unroll
            for (int im = 0; im < 2; im++) {
                int m = wm * 32 + im * 16 + g;
                af[im][0] = __float_as_uint(As[m * SA + k8 + t4]);
                af[im][1] = __float_as_uint(As[(m + 8) * SA + k8 + t4]);
                af[im][2] = __float_as_uint(As[m * SA + k8 + t4 + 4]);
                af[im][3] = __float_as_uint(As[(m + 8) * SA + k8 + t4 + 4]);
            }
#pragma unroll
            for (int in = 0; in < 8; in++) {
                int n = wn * 64 + in * 8 + g;
                bf[in][0] = __float_as_uint(Bs[n * SA + k8 + t4]);
                bf[in][1] = __float_as_uint(Bs[n * SA + k8 + t4 + 4]);
            }
#pragma unroll
            for (int im = 0; im < 2; im++)
#pragma unroll
                for (int in = 0; in < 8; in++)
                    mma8(acc[im][in], af[im], bf[in]);
        }
    }
#undef LD_NT

#pragma unroll
    for (int im = 0; im < 2; im++) {
        int m0 = wm * 32 + im * 16 + g;
#pragma unroll
        for (int in = 0; in < 8; in++) {
            int n0 = wn * 64 + in * 8 + t4 * 2;
            *(float2*)(C + m0 * 128 + n0)       = make_float2(acc[im][in][0], acc[im][in][1]);
            *(float2*)(C + (m0 + 8) * 128 + n0) = make_float2(acc[im][in][2], acc[im][in][3]);
        }
    }
}

__global__ __launch_bounds__(256) void reduce_ctx()
{
    const long long i = (long long)blockIdx.x * 256 + threadIdx.x;
    const long long total = (long long)BDIM * HEADS * DIMH * DIMH;
    if (i >= total) return;
    const float* p = &g_ctx_part[0][0][0][0];
    float s = 0.f;
#pragma unroll
    for (int k = 0; k < KSPLIT; k++) s += p[(long long)k * total + i];
    (&g_ctxT[0][0][0])[i] = rtf32(s);
}

// ---------------------------------------------------------------------------
// In-place softmax over n (4096) for k rows of g_qkv; stores tf32-rounded.
// ---------------------------------------------------------------------------
__global__ __launch_bounds__(256) void softmax_k()
{
    const int r = blockIdx.x;
    const int b = r >> 9;
    const int o = 512 + (r & 511);
    float* row = g_qkv + ((long long)b * QKVR + o) * NPIX;

    __shared__ float sh[NPIX];
    __shared__ float red[8];
    const int tid = threadIdx.x;

    float mx = -1e30f;
    for (int i = tid; i < NPIX; i += 256) {
        float v = row[i];
        sh[i] = v;
        mx = fmaxf(mx, v);
    }
#pragma unroll
    for (int off = 16; off; off >>= 1) mx = fmaxf(mx, __shfl_xor_sync(0xffffffffu, mx, off));
    if ((tid & 31) == 0) red[tid >> 5] = mx;
    __syncthreads();
    float m = red[0];
#pragma unroll
    for (int i = 1; i < 8; i++) m = fmaxf(m, red[i]);
    __syncthreads();

    float s = 0.f;
    for (int i = tid; i < NPIX; i += 256) {
        float e = __expf(sh[i] - m);
        sh[i] = e;
        s += e;
    }
#pragma unroll
    for (int off = 16; off; off >>= 1) s += __shfl_xor_sync(0xffffffffu, s, off);
    if ((tid & 31) == 0) red[tid >> 5] = s;
    __syncthreads();
    float tot = 0.f;
#pragma unroll
    for (int i = 0; i < 8; i++) tot += red[i];
    const float inv = 1.f / tot;

    for (int i = tid; i < NPIX; i += 256) row[i] = rtf32(sh[i] * inv);
}

// ---------------------------------------------------------------------------
extern "C" void kernel_launch(void* const* d_in, const int* in_sizes, int n_in,
                              void* d_out, int out_size)
{
    (void)in_sizes; (void)n_in; (void)out_size;
    const float* x     = (const float*)d_in[0];
    const float* w_qkv = (const float*)d_in[1];
    const float* w_out = (const float*)d_in[2];
    const float* b_out = (const float*)d_in[3];
    float* out = (float*)d_out;

    float *qkv_p, *attn_p, *ctxT_p, *xr_p, *wq_p, *wo_p;
    cudaGetSymbolAddress((void**)&qkv_p,  g_qkv);
    cudaGetSymbolAddress((void**)&attn_p, g_attn);
    cudaGetSymbolAddress((void**)&ctxT_p, g_ctxT);
    cudaGetSymbolAddress((void**)&xr_p,   g_xr);
    cudaGetSymbolAddress((void**)&wq_p,   g_wq);
    cudaGetSymbolAddress((void**)&wo_p,   g_wo);

    cudaFuncSetAttribute((const void*)gemm_nn<true>,
                         cudaFuncAttributeMaxDynamicSharedMemorySize, SMEM_NN);
    cudaFuncSetAttribute((const void*)gemm_nn<false>,
                         cudaFuncAttributeMaxDynamicSharedMemorySize, SMEM_NN);
    cudaFuncSetAttribute((const void*)gemm_nt_ctx,
                         cudaFuncAttributeMaxDynamicSharedMemorySize, SMEM_NT);

    dim3 blk(256);

    // pre-round inputs to tf32
    round_tf32<<<(BDIM * CIN * NPIX / 4 + 255) / 256, blk>>>(x, xr_p, BDIM * CIN * NPIX / 4);
    round_tf32<<<(QKVR * CIN / 4 + 255) / 256, blk>>>(w_qkv, wq_p, QKVR * CIN / 4);
    round_tf32<<<(CIN * HID / 4 + 255) / 256, blk>>>(w_out, wo_p, CIN * HID / 4);

    // GEMM1: qkv[b] = w_qkv @ x[b]   (round output)
    gemm_nn<true><<<dim3(NPIX / 128, QKVR / 128, BDIM), blk, SMEM_NN>>>(
        wq_p, 0, 0,
        xr_p, (long long)CIN * NPIX, 0,
        qkv_p, (long long)QKVR * NPIX, 0,
        nullptr, 1, NPIX, CIN);

    // softmax over n on k region (rounds output)
    softmax_k<<<BDIM * HEADS * DIMH, blk>>>();

    // GEMM2 (NT split-K) + rounded reduce
    gemm_nt_ctx<<<dim3(KSPLIT, BDIM * HEADS), blk, SMEM_NT>>>();
    reduce_ctx<<<(BDIM * HEADS * DIMH * DIMH) / 256, blk>>>();

    // GEMM3: attn[b,h] = ctxT[b,h] @ q[b,h]   (round output)
    gemm_nn<true><<<dim3(NPIX / 128, 1, BDIM * HEADS), blk, SMEM_NN>>>(
        ctxT_p, (long long)HEADS * DIMH * DIMH, (long long)DIMH * DIMH,
        qkv_p, (long long)QKVR * NPIX, (long long)DIMH * NPIX,
        attn_p, (long long)HID * NPIX, (long long)DIMH * NPIX,
        nullptr, HEADS, NPIX, DIMH);

    // GEMM4: out[b] = w_out @ attn[b] + b_out   (full fp32)
    gemm_nn<false><<<dim3(NPIX / 128, CIN / 128, BDIM), blk, SMEM_NN>>>(
        wo_p, 0, 0,
        attn_p, (long long)HID * NPIX, 0,
        out, (long long)CIN * NPIX, 0,
        b_out, 1, NPIX, HID);
}

// round 5
// speedup vs baseline: 1.3053x; 1.1006x over previous
#include <cuda_runtime.h>
#include <cstdint>

// ---------------------------------------------------------------------------
// LinearAttention, tf32 mma.sync m16n8k8, cp.async 3-stage, BK=32.
// tcgen05 unavailable (harness PTX targets family sm_103, not sm_103a).
//   GEMM1: qkv = w_qkv @ x        (NN, B=x converted in fragment load)
//   softmax over n on k rows      (rounds out)
//   GEMM2: ctxT = v @ k^T         (NT, split-K 8) + rounded reduce
//   GEMM3: attn = ctxT @ q        (NN, rounds out)
//   GEMM4: out  = w_out @ attn+b  (NN, fp32 out)
// ---------------------------------------------------------------------------

#define BDIM   8
#define CIN    256
#define NPIX   4096
#define HEADS  4
#define DIMH   128
#define HID    512
#define QKVR   1536
#define KSPLIT 8

#define SAS    36            // A smem stride (floats), [m][k], 144B (16B-aligned)
#define SBS    136           // B smem stride (floats), [k][n], 544B
#define ASTGF  (128 * SAS)   // 4608 floats
#define BSTGF  (32 * SBS)    // 4352 floats
#define SMEM_NN (3 * (ASTGF + BSTGF) * 4)   // 107520
#define SMEM_NT (3 * 2 * ASTGF * 4)         // 110592

__device__ float g_qkv [(size_t)BDIM * QKVR * NPIX];
__device__ float g_attn[(size_t)BDIM * HID  * NPIX];
__device__ float g_ctx_part[KSPLIT][BDIM * HEADS][DIMH][DIMH];
__device__ float g_ctxT[BDIM * HEADS][DIMH][DIMH];
__device__ float g_wq  [QKVR * CIN];
__device__ float g_wo  [CIN * HID];

__device__ __forceinline__ float rtf32(float x) {
    uint32_t u;
    asm("cvt.rna.tf32.f32 %0, %1;" : "=r"(u) : "f"(x));
    return __uint_as_float(u);
}
__device__ __forceinline__ uint32_t rtf32u(float x) {
    uint32_t u;
    asm("cvt.rna.tf32.f32 %0, %1;" : "=r"(u) : "f"(x));
    return u;
}
__device__ __forceinline__ void cpa16(uint32_t d, const float* s) {
    asm volatile("cp.async.cg.shared.global [%0], [%1], 16;\n" :: "r"(d), "l"(s));
}
__device__ __forceinline__ void cp_commit() { asm volatile("cp.async.commit_group;\n"); }
template<int N> __device__ __forceinline__ void cp_wait() {
    asm volatile("cp.async.wait_group %0;\n" :: "n"(N));
}

__device__ __forceinline__ void mma8(float c[4], const uint32_t a[4], const uint32_t b[2]) {
    asm volatile(
        "mma.sync.aligned.m16n8k8.row.col.f32.tf32.tf32.f32 "
        "{%0,%1,%2,%3}, {%4,%5,%6,%7}, {%8,%9}, {%0,%1,%2,%3};"
        : "+f"(c[0]), "+f"(c[1]), "+f"(c[2]), "+f"(c[3])
        : "r"(a[0]), "r"(a[1]), "r"(a[2]), "r"(a[3]), "r"(b[0]), "r"(b[1]));
}

// ---------------------------------------------------------------------------
__global__ __launch_bounds__(256) void round_tf32(
    const float* __restrict__ in, float* __restrict__ out, int n4)
{
    int i = blockIdx.x * 256 + threadIdx.x;
    if (i < n4) {
        float4 v = ((const float4*)in)[i];
        v.x = rtf32(v.x); v.y = rtf32(v.y); v.z = rtf32(v.z); v.w = rtf32(v.w);
        ((float4*)out)[i] = v;
    }
}

// ---------------------------------------------------------------------------
// NN GEMM: C = A[M,K]@B[K,N] (+bias). 128x128 tile, BK=32, 3-stage cp.async.
// CVTB: convert B fragments to tf32 at load (B source is raw fp32).
// ---------------------------------------------------------------------------
template<bool ROUND, bool CVTB>
__global__ __launch_bounds__(256, 2) void gemm_nn(
    const float* __restrict__ A, long long sA1, long long sA2, int lda,
    const float* __restrict__ B, long long sB1, long long sB2,
    float*       __restrict__ C, long long sC1, long long sC2,
    const float* __restrict__ bias,
    int zdiv, int N, int K)
{
    extern __shared__ float sm[];
    float* Asm = sm;                 // [3][128][SAS]
    float* Bsm = sm + 3 * ASTGF;     // [3][32][SBS]

    const int bm = blockIdx.y, bn = blockIdx.x;
    const int zo = blockIdx.z / zdiv, zi = blockIdx.z % zdiv;
    A += zo * sA1 + zi * sA2;
    B += zo * sB1 + zi * sB2;
    C += zo * sC1 + zi * sC2;

    const int tid  = threadIdx.x;
    const int lane = tid & 31, warp = tid >> 5;
    const int g    = lane >> 2, t4 = lane & 3;
    const int wm   = warp & 3,  wn = warp >> 2;

    const float* Ag = A + (long long)bm * 128 * lda;
    const float* Bg = B + bn * 128;

    const uint32_t asm0 = (uint32_t)__cvta_generic_to_shared(Asm);
    const uint32_t bsm0 = (uint32_t)__cvta_generic_to_shared(Bsm);

#define LD_NN(st, kk) do {                                                        \
    uint32_t ab = asm0 + (uint32_t)(st) * (ASTGF * 4);                            \
    uint32_t bb = bsm0 + (uint32_t)(st) * (BSTGF * 4);                            \
    _Pragma("unroll")                                                             \
    for (int t = 0; t < 4; t++) {                                                 \
        int idx = t * 256 + tid;                                                  \
        int row = idx >> 3, ch = (idx & 7) * 4;                                   \
        cpa16(ab + (uint32_t)(row * SAS + ch) * 4,                                \
              Ag + (long long)row * lda + (kk) + ch);                             \
        int kr = idx >> 5, nq = (idx & 31) * 4;                                   \
        cpa16(bb + (uint32_t)(kr * SBS + nq) * 4,                                 \
              Bg + (long long)((kk) + kr) * N + nq);                              \
    }                                                                             \
    cp_commit();                                                                  \
} while (0)

    float acc[2][8][4] = {};
    const int niter = K >> 5;

    LD_NN(0, 0);
    LD_NN(1, 32);

    for (int it = 0; it < niter; ++it) {
        cp_wait<1>();
        __syncthreads();
        const int ls = it + 2;
        if (ls < niter) { LD_NN(ls % 3, ls * 32); }
        else            { cp_commit(); }

        const float* As = Asm + (it % 3) * ASTGF;
        const float* Bs = Bsm + (it % 3) * BSTGF;

#pragma unroll
        for (int k8 = 0; k8 < 32; k8 += 8) {
            uint32_t af[2][4], bf[8][2];
#pragma unroll
            for (int im = 0; im < 2; im++) {
                int m = wm * 32 + im * 16 + g;
                af[im][0] = __float_as_uint(As[m * SAS + k8 + t4]);
                af[im][1] = __float_as_uint(As[(m + 8) * SAS + k8 + t4]);
                af[im][2] = __float_as_uint(As[m * SAS + k8 + t4 + 4]);
                af[im][3] = __float_as_uint(As[(m + 8) * SAS + k8 + t4 + 4]);
            }
#pragma unroll
            for (int in = 0; in < 8; in++) {
                int n = wn * 64 + in * 8 + g;
                if (CVTB) {
                    bf[in][0] = rtf32u(Bs[(k8 + t4) * SBS + n]);
                    bf[in][1] = rtf32u(Bs[(k8 + t4 + 4) * SBS + n]);
                } else {
                    bf[in][0] = __float_as_uint(Bs[(k8 + t4) * SBS + n]);
                    bf[in][1] = __float_as_uint(Bs[(k8 + t4 + 4) * SBS + n]);
                }
            }
#pragma unroll
            for (int im = 0; im < 2; im++)
#pragma unroll
                for (int in = 0; in < 8; in++)
                    mma8(acc[im][in], af[im], bf[in]);
        }
    }
#undef LD_NN

#pragma unroll
    for (int im = 0; im < 2; im++) {
        int m0 = bm * 128 + wm * 32 + im * 16 + g;
        float bv0 = bias ? bias[m0]     : 0.f;
        float bv1 = bias ? bias[m0 + 8] : 0.f;
#pragma unroll
        for (int in = 0; in < 8; in++) {
            int n0 = bn * 128 + wn * 64 + in * 8 + t4 * 2;
            float v0 = acc[im][in][0] + bv0, v1 = acc[im][in][1] + bv0;
            float v2 = acc[im][in][2] + bv1, v3 = acc[im][in][3] + bv1;
            if (ROUND) { v0 = rtf32(v0); v1 = rtf32(v1); v2 = rtf32(v2); v3 = rtf32(v3); }
            *(float2*)(C + (long long)m0 * N + n0)       = make_float2(v0, v1);
            *(float2*)(C + (long long)(m0 + 8) * N + n0) = make_float2(v2, v3);
        }
    }
}

// ---------------------------------------------------------------------------
// GEMM2 (NT, split-K): ctx_part[slice][bh][e][d] = sum_{n in slice} v[e,n]k[d,n]
// ---------------------------------------------------------------------------
__global__ __launch_bounds__(256, 2) void gemm_nt_ctx()
{
    extern __shared__ float sm[];
    float* Asm = sm;                 // [3][128][SAS] (v: [e][k])
    float* Bsm = sm + 3 * ASTGF;     // [3][128][SAS] (k: [d][k])

    const int slice = blockIdx.x;
    const int bh    = blockIdx.y;
    const int b = bh >> 2, h = bh & 3;

    const float* Ag = g_qkv + ((long long)b * QKVR + 1024 + h * 128) * NPIX;
    const float* Bg = g_qkv + ((long long)b * QKVR +  512 + h * 128) * NPIX;
    float* C = &g_ctx_part[slice][bh][0][0];

    const int tid  = threadIdx.x;
    const int lane = tid & 31, warp = tid >> 5;
    const int g    = lane >> 2, t4 = lane & 3;
    const int wm   = warp & 3,  wn = warp >> 2;

    const uint32_t asm0 = (uint32_t)__cvta_generic_to_shared(Asm);
    const uint32_t bsm0 = (uint32_t)__cvta_generic_to_shared(Bsm);

#define LD_NT(st, kk) do {                                                        \
    uint32_t ab = asm0 + (uint32_t)(st) * (ASTGF * 4);                            \
    uint32_t bb = bsm0 + (uint32_t)(st) * (ASTGF * 4);                            \
    _Pragma("unroll")                                                             \
    for (int t = 0; t < 4; t++) {                                                 \
        int idx = t * 256 + tid;                                                  \
        int row = idx >> 3, ch = (idx & 7) * 4;                                   \
        uint32_t so = (uint32_t)(row * SAS + ch) * 4;                             \
        cpa16(ab + so, Ag + (long long)row * NPIX + (kk) + ch);                   \
        cpa16(bb + so, Bg + (long long)row * NPIX + (kk) + ch);                   \
    }                                                                             \
    cp_commit();                                                                  \
} while (0)

    float acc[2][8][4] = {};
    const int kbeg  = slice * (NPIX / KSPLIT);
    const int niter = (NPIX / KSPLIT) >> 5;   // 16

    LD_NT(0, kbeg);
    LD_NT(1, kbeg + 32);

    for (int it = 0; it < niter; ++it) {
        cp_wait<1>();
        __syncthreads();
        const int ls = it + 2;
        if (ls < niter) { LD_NT(ls % 3, kbeg + ls * 32); }
        else            { cp_commit(); }

        const float* As = Asm + (it % 3) * ASTGF;
        const float* Bs = Bsm + (it % 3) * ASTGF;

#pragma unroll
        for (int k8 = 0; k8 < 32; k8 += 8) {
            uint32_t af[2][4], bf[8][2];
#pragma unroll
            for (int im = 0; im < 2; im++) {
                int m = wm * 32 + im * 16 + g;
                af[im][0] = __float_as_uint(As[m * SAS + k8 + t4]);
                af[im][1] = __float_as_uint(As[(m + 8) * SAS + k8 + t4]);
                af[im][2] = __float_as_uint(As[m * SAS + k8 + t4 + 4]);
                af[im][3] = __float_as_uint(As[(m + 8) * SAS + k8 + t4 + 4]);
            }
#pragma unroll
            for (int in = 0; in < 8; in++) {
                int n = wn * 64 + in * 8 + g;
                bf[in][0] = __float_as_uint(Bs[n * SAS + k8 + t4]);
                bf[in][1] = __float_as_uint(Bs[n * SAS + k8 + t4 + 4]);
            }
#pragma unroll
            for (int im = 0; im < 2; im++)
#pragma unroll
                for (int in = 0; in < 8; in++)
                    mma8(acc[im][in], af[im], bf[in]);
        }
    }
#undef LD_NT

#pragma unroll
    for (int im = 0; im < 2; im++) {
        int m0 = wm * 32 + im * 16 + g;
#pragma unroll
        for (int in = 0; in < 8; in++) {
            int n0 = wn * 64 + in * 8 + t4 * 2;
            *(float2*)(C + m0 * 128 + n0)       = make_float2(acc[im][in][0], acc[im][in][1]);
            *(float2*)(C + (m0 + 8) * 128 + n0) = make_float2(acc[im][in][2], acc[im][in][3]);
        }
    }
}

__global__ __launch_bounds__(256) void reduce_ctx()
{
    const long long i = (long long)blockIdx.x * 256 + threadIdx.x;
    const long long total = (long long)BDIM * HEADS * DIMH * DIMH;
    if (i >= total) return;
    const float* p = &g_ctx_part[0][0][0][0];
    float s = 0.f;
#pragma unroll
    for (int k = 0; k < KSPLIT; k++) s += p[(long long)k * total + i];
    (&g_ctxT[0][0][0])[i] = rtf32(s);
}

// ---------------------------------------------------------------------------
__global__ __launch_bounds__(256) void softmax_k()
{
    const int r = blockIdx.x;
    const int b = r >> 9;
    const int o = 512 + (r & 511);
    float* row = g_qkv + ((long long)b * QKVR + o) * NPIX;

    __shared__ float sh[NPIX];
    __shared__ float red[8];
    const int tid = threadIdx.x;

    float mx = -1e30f;
    for (int i = tid; i < NPIX; i += 256) {
        float v = row[i];
        sh[i] = v;
        mx = fmaxf(mx, v);
    }
#pragma unroll
    for (int off = 16; off; off >>= 1) mx = fmaxf(mx, __shfl_xor_sync(0xffffffffu, mx, off));
    if ((tid & 31) == 0) red[tid >> 5] = mx;
    __syncthreads();
    float m = red[0];
#pragma unroll
    for (int i = 1; i < 8; i++) m = fmaxf(m, red[i]);
    __syncthreads();

    float s = 0.f;
    for (int i = tid; i < NPIX; i += 256) {
        float e = __expf(sh[i] - m);
        sh[i] = e;
        s += e;
    }
#pragma unroll
    for (int off = 16; off; off >>= 1) s += __shfl_xor_sync(0xffffffffu, s, off);
    if ((tid & 31) == 0) red[tid >> 5] = s;
    __syncthreads();
    float tot = 0.f;
#pragma unroll
    for (int i = 0; i < 8; i++) tot += red[i];
    const float inv = 1.f / tot;

    for (int i = tid; i < NPIX; i += 256) row[i] = rtf32(sh[i] * inv);
}

// ---------------------------------------------------------------------------
extern "C" void kernel_launch(void* const* d_in, const int* in_sizes, int n_in,
                              void* d_out, int out_size)
{
    (void)in_sizes; (void)n_in; (void)out_size;
    const float* x     = (const float*)d_in[0];
    const float* w_qkv = (const float*)d_in[1];
    const float* w_out = (const float*)d_in[2];
    const float* b_out = (const float*)d_in[3];
    float* out = (float*)d_out;

    float *qkv_p, *attn_p, *ctxT_p, *wq_p, *wo_p;
    cudaGetSymbolAddress((void**)&qkv_p,  g_qkv);
    cudaGetSymbolAddress((void**)&attn_p, g_attn);
    cudaGetSymbolAddress((void**)&ctxT_p, g_ctxT);
    cudaGetSymbolAddress((void**)&wq_p,   g_wq);
    cudaGetSymbolAddress((void**)&wo_p,   g_wo);

    cudaFuncSetAttribute((const void*)gemm_nn<true, true>,
                         cudaFuncAttributeMaxDynamicSharedMemorySize, SMEM_NN);
    cudaFuncSetAttribute((const void*)gemm_nn<true, false>,
                         cudaFuncAttributeMaxDynamicSharedMemorySize, SMEM_NN);
    cudaFuncSetAttribute((const void*)gemm_nn<false, false>,
                         cudaFuncAttributeMaxDynamicSharedMemorySize, SMEM_NN);
    cudaFuncSetAttribute((const void*)gemm_nt_ctx,
                         cudaFuncAttributeMaxDynamicSharedMemorySize, SMEM_NT);

    dim3 blk(256);

    // pre-round weights only (x is converted inside GEMM1 fragment loads)
    round_tf32<<<(QKVR * CIN / 4 + 255) / 256, blk>>>(w_qkv, wq_p, QKVR * CIN / 4);
    round_tf32<<<(CIN * HID / 4 + 255) / 256, blk>>>(w_out, wo_p, CIN * HID / 4);

    // GEMM1: qkv[b] = w_qkv @ x[b]   (round out; B converted in-loop)
    gemm_nn<true, true><<<dim3(NPIX / 128, QKVR / 128, BDIM), blk, SMEM_NN>>>(
        wq_p, 0, 0, CIN,
        x, (long long)CIN * NPIX, 0,
        qkv_p, (long long)QKVR * NPIX, 0,
        nullptr, 1, NPIX, CIN);

    softmax_k<<<BDIM * HEADS * DIMH, blk>>>();

    gemm_nt_ctx<<<dim3(KSPLIT, BDIM * HEADS), blk, SMEM_NT>>>();
    reduce_ctx<<<(BDIM * HEADS * DIMH * DIMH) / 256, blk>>>();

    // GEMM3: attn[b,h] = ctxT[b,h] @ q[b,h]   (round out)
    gemm_nn<true, false><<<dim3(NPIX / 128, 1, BDIM * HEADS), blk, SMEM_NN>>>(
        ctxT_p, (long long)HEADS * DIMH * DIMH, (long long)DIMH * DIMH, DIMH,
        qkv_p, (long long)QKVR * NPIX, (long long)DIMH * NPIX,
        attn_p, (long long)HID * NPIX, (long long)DIMH * NPIX,
        nullptr, HEADS, NPIX, DIMH);

    // GEMM4: out[b] = w_out @ attn[b] + b_out   (fp32 out)
    gemm_nn<false, false><<<dim3(NPIX / 128, CIN / 128, BDIM), blk, SMEM_NN>>>(
        wo_p, 0, 0, HID,
        attn_p, (long long)HID * NPIX, 0,
        out, (long long)CIN * NPIX, 0,
        b_out, 1, NPIX, HID);
}

// round 6
// speedup vs baseline: 2.3592x; 1.8074x over previous
#include <cuda_runtime.h>
#include <cuda_fp16.h>
#include <cstdint>

// ---------------------------------------------------------------------------
// LinearAttention, fp16 mma.sync m16n8k16 (fp32 accum) + ldmatrix + cp.async.
//   cvt: x, w_qkv, w_out -> fp16 (rn)
//   GEMM1: qkv = w_qkv @ x        (NN) -> fp16
//   softmax over n on k rows (fp16 in/out, fp32 math, register-resident)
//   GEMM2: ctxT = v @ k^T         (NT, split-K 8) -> fp32 partials -> fp16
//   GEMM3: attn = ctxT @ q        (NN) -> fp16
//   GEMM4: out  = w_out @ attn +b (NN) -> fp32
// ---------------------------------------------------------------------------

#define BDIM   8
#define CIN    256
#define NPIX   4096
#define HEADS  4
#define DIMH   128
#define HID    512
#define QKVR   1536
#define KSPLIT 8

#define SAH    40                 // A smem stride (halfs): 80B
#define SBH    136                // B smem stride (halfs): 272B
#define ASTGH  (128 * SAH)        // 5120 halfs = 10240 B
#define BSTGH  (32 * SBH)         // 4352 halfs = 8704 B
#define SMEM_NN (3 * (ASTGH + BSTGH) * 2)   // 56832
#define SMEM_NT (3 * 2 * ASTGH * 2)         // 61440

__device__ __half g_qkvh[(size_t)BDIM * QKVR * NPIX];
__device__ __half g_attnh[(size_t)BDIM * HID * NPIX];
__device__ float  g_ctx_part[KSPLIT][BDIM * HEADS][DIMH][DIMH];
__device__ __half g_ctxTh[BDIM * HEADS][DIMH][DIMH];
__device__ __half g_xh [(size_t)BDIM * CIN * NPIX];
__device__ __half g_wqh[QKVR * CIN];
__device__ __half g_woh[CIN * HID];

// ---------------- helpers ----------------
__device__ __forceinline__ void cpa16(uint32_t d, const void* s) {
    asm volatile("cp.async.cg.shared.global [%0], [%1], 16;\n" :: "r"(d), "l"(s));
}
__device__ __forceinline__ void cp_commit() { asm volatile("cp.async.commit_group;\n"); }
template<int N> __device__ __forceinline__ void cp_wait() {
    asm volatile("cp.async.wait_group %0;\n" :: "n"(N));
}
__device__ __forceinline__ void ldsm_x4(uint32_t r[4], uint32_t a) {
    asm volatile("ldmatrix.sync.aligned.m8n8.x4.shared.b16 {%0,%1,%2,%3}, [%4];"
        : "=r"(r[0]), "=r"(r[1]), "=r"(r[2]), "=r"(r[3]) : "r"(a));
}
__device__ __forceinline__ void ldsm_x4t(uint32_t r[4], uint32_t a) {
    asm volatile("ldmatrix.sync.aligned.m8n8.x4.trans.shared.b16 {%0,%1,%2,%3}, [%4];"
        : "=r"(r[0]), "=r"(r[1]), "=r"(r[2]), "=r"(r[3]) : "r"(a));
}
__device__ __forceinline__ void mma16(float c[4], const uint32_t a[4], const uint32_t b0, const uint32_t b1) {
    asm volatile(
        "mma.sync.aligned.m16n8k16.row.col.f32.f16.f16.f32 "
        "{%0,%1,%2,%3}, {%4,%5,%6,%7}, {%8,%9}, {%0,%1,%2,%3};"
        : "+f"(c[0]), "+f"(c[1]), "+f"(c[2]), "+f"(c[3])
        : "r"(a[0]), "r"(a[1]), "r"(a[2]), "r"(a[3]), "r"(b0), "r"(b1));
}

// ---------------------------------------------------------------------------
__global__ __launch_bounds__(256) void f2h(
    const float* __restrict__ in, __half* __restrict__ out, int n4)
{
    int i = blockIdx.x * 256 + threadIdx.x;
    if (i < n4) {
        float4 v = ((const float4*)in)[i];
        __half2 h0 = __floats2half2_rn(v.x, v.y);
        __half2 h1 = __floats2half2_rn(v.z, v.w);
        uint2 u;
        u.x = *(uint32_t*)&h0;
        u.y = *(uint32_t*)&h1;
        ((uint2*)out)[i] = u;
    }
}

// ---------------------------------------------------------------------------
// NN GEMM fp16: C = A[M,K]@B[K,N] (+bias). 128x128 tile, BK=32, 3-stage.
// HALF_OUT: C is __half (no bias); else float (+bias).
// ---------------------------------------------------------------------------
template<bool HALF_OUT>
__global__ __launch_bounds__(256, 2) void gemm_nn(
    const __half* __restrict__ A, long long sA1, long long sA2, int lda,
    const __half* __restrict__ B, long long sB1, long long sB2,
    void*         __restrict__ Cv, long long sC1, long long sC2,
    const float* __restrict__ bias,
    int zdiv, int N, int K)
{
    extern __shared__ __half sm[];
    __half* Asm = sm;                 // [3][128][SAH]
    __half* Bsm = sm + 3 * ASTGH;     // [3][32][SBH]

    const int bm = blockIdx.y, bn = blockIdx.x;
    const int zo = blockIdx.z / zdiv, zi = blockIdx.z % zdiv;
    A += zo * sA1 + zi * sA2;
    B += zo * sB1 + zi * sB2;

    const int tid  = threadIdx.x;
    const int lane = tid & 31, warp = tid >> 5;
    const int g    = lane >> 2, t4 = lane & 3;
    const int wm   = warp & 3,  wn = warp >> 2;
    const int l15  = lane & 15, lh = lane >> 4;

    const __half* Ag = A + (long long)bm * 128 * lda;
    const __half* Bg = B + bn * 128;

    const uint32_t asm0 = (uint32_t)__cvta_generic_to_shared(Asm);
    const uint32_t bsm0 = (uint32_t)__cvta_generic_to_shared(Bsm);

#define LD_NN(st, kk) do {                                                       \
    uint32_t ab = asm0 + (uint32_t)(st) * (ASTGH * 2);                           \
    uint32_t bb = bsm0 + (uint32_t)(st) * (BSTGH * 2);                           \
    _Pragma("unroll")                                                            \
    for (int t = 0; t < 2; t++) {                                                \
        int idx = t * 256 + tid;                                                 \
        int row = idx >> 2, ch = idx & 3;                                        \
        cpa16(ab + (uint32_t)(row * SAH + ch * 8) * 2,                           \
              Ag + (long long)row * lda + (kk) + ch * 8);                        \
        int kr = idx >> 4, nc = idx & 15;                                        \
        cpa16(bb + (uint32_t)(kr * SBH + nc * 8) * 2,                            \
              Bg + (long long)((kk) + kr) * N + nc * 8);                         \
    }                                                                            \
    cp_commit();                                                                 \
} while (0)

    float acc[2][8][4] = {};
    const int niter = K >> 5;

    LD_NN(0, 0);
    LD_NN(1, 32);

    for (int it = 0; it < niter; ++it) {
        cp_wait<1>();
        __syncthreads();
        const int ls = it + 2;
        if (ls < niter) { LD_NN(ls % 3, ls * 32); }
        else            { cp_commit(); }

        const uint32_t Asb = asm0 + (uint32_t)(it % 3) * (ASTGH * 2);
        const uint32_t Bsb = bsm0 + (uint32_t)(it % 3) * (BSTGH * 2);

#pragma unroll
        for (int k16 = 0; k16 < 32; k16 += 16) {
            uint32_t af[2][4], bf[8][2];
#pragma unroll
            for (int im = 0; im < 2; im++) {
                int m = wm * 32 + im * 16 + l15;
                ldsm_x4(af[im], Asb + (uint32_t)(m * SAH + k16 + lh * 8) * 2);
            }
#pragma unroll
            for (int pr = 0; pr < 4; pr++) {
                int n0 = wn * 64 + pr * 16;
                uint32_t bq[4];
                ldsm_x4t(bq, Bsb + (uint32_t)((k16 + l15) * SBH + n0 + lh * 8) * 2);
                bf[2 * pr][0] = bq[0]; bf[2 * pr][1] = bq[1];
                bf[2 * pr + 1][0] = bq[2]; bf[2 * pr + 1][1] = bq[3];
            }
#pragma unroll
            for (int im = 0; im < 2; im++)
#pragma unroll
                for (int in = 0; in < 8; in++)
                    mma16(acc[im][in], af[im], bf[in][0], bf[in][1]);
        }
    }
#undef LD_NN

    if (HALF_OUT) {
        __half* C = (__half*)Cv + zo * sC1 + zi * sC2;
#pragma unroll
        for (int im = 0; im < 2; im++) {
            int m0 = bm * 128 + wm * 32 + im * 16 + g;
#pragma unroll
            for (int in = 0; in < 8; in++) {
                int n0 = bn * 128 + wn * 64 + in * 8 + t4 * 2;
                __half2 h0 = __floats2half2_rn(acc[im][in][0], acc[im][in][1]);
                __half2 h1 = __floats2half2_rn(acc[im][in][2], acc[im][in][3]);
                *(__half2*)(C + (long long)m0 * N + n0)       = h0;
                *(__half2*)(C + (long long)(m0 + 8) * N + n0) = h1;
            }
        }
    } else {
        float* C = (float*)Cv + zo * sC1 + zi * sC2;
#pragma unroll
        for (int im = 0; im < 2; im++) {
            int m0 = bm * 128 + wm * 32 + im * 16 + g;
            float bv0 = bias ? bias[m0]     : 0.f;
            float bv1 = bias ? bias[m0 + 8] : 0.f;
#pragma unroll
            for (int in = 0; in < 8; in++) {
                int n0 = bn * 128 + wn * 64 + in * 8 + t4 * 2;
                *(float2*)(C + (long long)m0 * N + n0) =
                    make_float2(acc[im][in][0] + bv0, acc[im][in][1] + bv0);
                *(float2*)(C + (long long)(m0 + 8) * N + n0) =
                    make_float2(acc[im][in][2] + bv1, acc[im][in][3] + bv1);
            }
        }
    }
}

// ---------------------------------------------------------------------------
// GEMM2 (NT, split-K): ctx_part[slice][bh][e][d] = sum_{n slice} v[e,n]k[d,n]
// ---------------------------------------------------------------------------
__global__ __launch_bounds__(256, 2) void gemm_nt_ctx()
{
    extern __shared__ __half sm[];
    __half* Asm = sm;                 // [3][128][SAH] (v: [e][k])
    __half* Bsm = sm + 3 * ASTGH;     // [3][128][SAH] (k: [d][k])

    const int slice = blockIdx.x;
    const int bh    = blockIdx.y;
    const int b = bh >> 2, h = bh & 3;

    const __half* Ag = g_qkvh + ((long long)b * QKVR + 1024 + h * 128) * NPIX;
    const __half* Bg = g_qkvh + ((long long)b * QKVR +  512 + h * 128) * NPIX;
    float* C = &g_ctx_part[slice][bh][0][0];

    const int tid  = threadIdx.x;
    const int lane = tid & 31, warp = tid >> 5;
    const int g    = lane >> 2, t4 = lane & 3;
    const int wm   = warp & 3,  wn = warp >> 2;
    const int l15  = lane & 15, lh = lane >> 4;

    const uint32_t asm0 = (uint32_t)__cvta_generic_to_shared(Asm);
    const uint32_t bsm0 = (uint32_t)__cvta_generic_to_shared(Bsm);

#define LD_NT(st, kk) do {                                                       \
    uint32_t ab = asm0 + (uint32_t)(st) * (ASTGH * 2);                           \
    uint32_t bb = bsm0 + (uint32_t)(st) * (ASTGH * 2);                           \
    _Pragma("unroll")                                                            \
    for (int t = 0; t < 2; t++) {                                                \
        int idx = t * 256 + tid;                                                 \
        int row = idx >> 2, ch = idx & 3;                                        \
        uint32_t so = (uint32_t)(row * SAH + ch * 8) * 2;                        \
        cpa16(ab + so, Ag + (long long)row * NPIX + (kk) + ch * 8);              \
        cpa16(bb + so, Bg + (long long)row * NPIX + (kk) + ch * 8);              \
    }                                                                            \
    cp_commit();                                                                 \
} while (0)

    float acc[2][8][4] = {};
    const int kbeg  = slice * (NPIX / KSPLIT);
    const int niter = (NPIX / KSPLIT) >> 5;   // 16

    LD_NT(0, kbeg);
    LD_NT(1, kbeg + 32);

    for (int it = 0; it < niter; ++it) {
        cp_wait<1>();
        __syncthreads();
        const int ls = it + 2;
        if (ls < niter) { LD_NT(ls % 3, kbeg + ls * 32); }
        else            { cp_commit(); }

        const uint32_t Asb = asm0 + (uint32_t)(it % 3) * (ASTGH * 2);
        const uint32_t Bsb = bsm0 + (uint32_t)(it % 3) * (ASTGH * 2);

#pragma unroll
        for (int k16 = 0; k16 < 32; k16 += 16) {
            uint32_t af[2][4], bf[8][2];
#pragma unroll
            for (int im = 0; im < 2; im++) {
                int m = wm * 32 + im * 16 + l15;
                ldsm_x4(af[im], Asb + (uint32_t)(m * SAH + k16 + lh * 8) * 2);
            }
#pragma unroll
            for (int pr = 0; pr < 4; pr++) {
                int d0 = wn * 64 + pr * 16;
                uint32_t bq[4];
                ldsm_x4(bq, Bsb + (uint32_t)((d0 + l15) * SAH + k16 + lh * 8) * 2);
                bf[2 * pr][0] = bq[0]; bf[2 * pr][1] = bq[2];   // tile d0..d0+7
                bf[2 * pr + 1][0] = bq[1]; bf[2 * pr + 1][1] = bq[3]; // d0+8..15
            }
#pragma unroll
            for (int im = 0; im < 2; im++)
#pragma unroll
                for (int in = 0; in < 8; in++)
                    mma16(acc[im][in], af[im], bf[in][0], bf[in][1]);
        }
    }
#undef LD_NT

#pragma unroll
    for (int im = 0; im < 2; im++) {
        int m0 = wm * 32 + im * 16 + g;
#pragma unroll
        for (int in = 0; in < 8; in++) {
            int n0 = wn * 64 + in * 8 + t4 * 2;
            *(float2*)(C + m0 * 128 + n0)       = make_float2(acc[im][in][0], acc[im][in][1]);
            *(float2*)(C + (m0 + 8) * 128 + n0) = make_float2(acc[im][in][2], acc[im][in][3]);
        }
    }
}

__global__ __launch_bounds__(256) void reduce_ctx()
{
    const long long i = (long long)blockIdx.x * 256 + threadIdx.x;
    const long long total = (long long)BDIM * HEADS * DIMH * DIMH;
    if (i >= total) return;
    const float* p = &g_ctx_part[0][0][0][0];
    float s = 0.f;
#pragma unroll
    for (int k = 0; k < KSPLIT; k++) s += p[(long long)k * total + i];
    (&g_ctxTh[0][0][0])[i] = __float2half_rn(s);
}

// ---------------------------------------------------------------------------
// Softmax over n (4096) on fp16 k rows; register-resident, fp32 math.
// ---------------------------------------------------------------------------
__global__ __launch_bounds__(256) void softmax_k()
{
    const int r = blockIdx.x;
    const int b = r >> 9;
    const int o = 512 + (r & 511);
    __half* row = g_qkvh + ((long long)b * QKVR + o) * NPIX;

    __shared__ float red[8];
    const int tid = threadIdx.x;

    uint4 u0 = ((const uint4*)row)[tid];
    uint4 u1 = ((const uint4*)row)[256 + tid];

    float v[16];
    {
        const __half2* h0 = (const __half2*)&u0;
        const __half2* h1 = (const __half2*)&u1;
#pragma unroll
        for (int i = 0; i < 4; i++) {
            float2 f0 = __half22float2(h0[i]);
            float2 f1 = __half22float2(h1[i]);
            v[2 * i] = f0.x; v[2 * i + 1] = f0.y;
            v[8 + 2 * i] = f1.x; v[8 + 2 * i + 1] = f1.y;
        }
    }

    float mx = v[0];
#pragma unroll
    for (int i = 1; i < 16; i++) mx = fmaxf(mx, v[i]);
#pragma unroll
    for (int off = 16; off; off >>= 1) mx = fmaxf(mx, __shfl_xor_sync(0xffffffffu, mx, off));
    if ((tid & 31) == 0) red[tid >> 5] = mx;
    __syncthreads();
    float m = red[0];
#pragma unroll
    for (int i = 1; i < 8; i++) m = fmaxf(m, red[i]);
    __syncthreads();

    float s = 0.f;
#pragma unroll
    for (int i = 0; i < 16; i++) { v[i] = __expf(v[i] - m); s += v[i]; }
#pragma unroll
    for (int off = 16; off; off >>= 1) s += __shfl_xor_sync(0xffffffffu, s, off);
    if ((tid & 31) == 0) red[tid >> 5] = s;
    __syncthreads();
    float tot = 0.f;
#pragma unroll
    for (int i = 0; i < 8; i++) tot += red[i];
    const float inv = 1.f / tot;

    uint4 w0, w1;
    __half2* o0 = (__half2*)&w0;
    __half2* o1 = (__half2*)&w1;
#pragma unroll
    for (int i = 0; i < 4; i++) {
        o0[i] = __floats2half2_rn(v[2 * i] * inv, v[2 * i + 1] * inv);
        o1[i] = __floats2half2_rn(v[8 + 2 * i] * inv, v[8 + 2 * i + 1] * inv);
    }
    ((uint4*)row)[tid] = w0;
    ((uint4*)row)[256 + tid] = w1;
}

// ---------------------------------------------------------------------------
extern "C" void kernel_launch(void* const* d_in, const int* in_sizes, int n_in,
                              void* d_out, int out_size)
{
    (void)in_sizes; (void)n_in; (void)out_size;
    const float* x     = (const float*)d_in[0];
    const float* w_qkv = (const float*)d_in[1];
    const float* w_out = (const float*)d_in[2];
    const float* b_out = (const float*)d_in[3];
    float* out = (float*)d_out;

    __half *qkv_p, *attn_p, *ctxT_p, *xh_p, *wq_p, *wo_p;
    cudaGetSymbolAddress((void**)&qkv_p,  g_qkvh);
    cudaGetSymbolAddress((void**)&attn_p, g_attnh);
    cudaGetSymbolAddress((void**)&ctxT_p, g_ctxTh);
    cudaGetSymbolAddress((void**)&xh_p,   g_xh);
    cudaGetSymbolAddress((void**)&wq_p,   g_wqh);
    cudaGetSymbolAddress((void**)&wo_p,   g_woh);

    cudaFuncSetAttribute((const void*)gemm_nn<true>,
                         cudaFuncAttributeMaxDynamicSharedMemorySize, SMEM_NN);
    cudaFuncSetAttribute((const void*)gemm_nn<false>,
                         cudaFuncAttributeMaxDynamicSharedMemorySize, SMEM_NN);
    cudaFuncSetAttribute((const void*)gemm_nt_ctx,
                         cudaFuncAttributeMaxDynamicSharedMemorySize, SMEM_NT);

    dim3 blk(256);

    // fp16 conversions
    f2h<<<(BDIM * CIN * NPIX / 4 + 255) / 256, blk>>>(x, xh_p, BDIM * CIN * NPIX / 4);
    f2h<<<(QKVR * CIN / 4 + 255) / 256, blk>>>(w_qkv, wq_p, QKVR * CIN / 4);
    f2h<<<(CIN * HID / 4 + 255) / 256, blk>>>(w_out, wo_p, CIN * HID / 4);

    // GEMM1: qkv[b] = w_qkv @ x[b]  -> fp16
    gemm_nn<true><<<dim3(NPIX / 128, QKVR / 128, BDIM), blk, SMEM_NN>>>(
        wq_p, 0, 0, CIN,
        xh_p, (long long)CIN * NPIX, 0,
        qkv_p, (long long)QKVR * NPIX, 0,
        nullptr, 1, NPIX, CIN);

    softmax_k<<<BDIM * HEADS * DIMH, blk>>>();

    gemm_nt_ctx<<<dim3(KSPLIT, BDIM * HEADS), blk, SMEM_NT>>>();
    reduce_ctx<<<(BDIM * HEADS * DIMH * DIMH) / 256, blk>>>();

    // GEMM3: attn[b,h] = ctxT[b,h] @ q[b,h]  -> fp16
    gemm_nn<true><<<dim3(NPIX / 128, 1, BDIM * HEADS), blk, SMEM_NN>>>(
        ctxT_p, (long long)HEADS * DIMH * DIMH, (long long)DIMH * DIMH, DIMH,
        qkv_p, (long long)QKVR * NPIX, (long long)DIMH * NPIX,
        attn_p, (long long)HID * NPIX, (long long)DIMH * NPIX,
        nullptr, HEADS, NPIX, DIMH);

    // GEMM4: out[b] = w_out @ attn[b] + b_out  -> fp32
    gemm_nn<false><<<dim3(NPIX / 128, CIN / 128, BDIM), blk, SMEM_NN>>>(
        wo_p, 0, 0, HID,
        attn_p, (long long)HID * NPIX, 0,
        out, (long long)CIN * NPIX, 0,
        b_out, 1, NPIX, HID);
}